// round 11
// baseline (speedup 1.0000x reference)
#include <cuda_runtime.h>
#include <cstdint>

#define NN 8192
#define KB 4096               // histogram buckets (fine sort -> tight bounds)
#define NCHUNK 256            // 256 chunks of 32 sorted candidates
#define GRP 4                 // chunks per probe group
#define NGRP (NCHUNK / GRP)

// Scratch (device globals — no allocation allowed in kernel_launch).
// Zero-initialized at load; every array is re-established each launch chain.
__device__ float    g_s[NN];          // s[j] by original index
__device__ float    g_wm[NN];         // wmax[j] by original index
__device__ int      g_bk[NN];         // bucket id by original index
__device__ __align__(16) int g_hist[KB];  // histogram (re-zeroed by scan for next run)
__device__ __align__(16) int g_cur[KB];   // exclusive offsets -> scatter cursors
__device__ float    g_ss[NN];         // s in bucket-sorted order
__device__ float    g_ws[NN];         // wmax in bucket-sorted order
__device__ int      g_idx[NN];        // original index in bucket-sorted order
__device__ unsigned g_csmin[NCHUNK];  // per-chunk min s   (positive-float bits, atomicMin)
__device__ unsigned g_cwmax[NCHUNK];  // per-chunk max w   (positive-float bits, atomicMax)
__device__ unsigned g_cnsmin[NCHUNK]; // per-chunk max -s*w (negative-float bits, atomicMin)

// K1: per-element s, wmax, bucket; histogram via spread global atomics
__global__ __launch_bounds__(128)
void bucket_kernel(const float* __restrict__ x, const float* __restrict__ Wphi) {
    int j = blockIdx.x * 128 + threadIdx.x;
    float s = x[3 * j + 0] + x[3 * j + 1] + x[3 * j + 2];
    float w0 = Wphi[j], w1 = Wphi[NN + j], w2 = Wphi[2 * NN + j];
    float w = fmaxf(w0, fmaxf(w1, w2));
    int b = (int)(s * (KB / 3.0f));
    b = max(0, min(KB - 1, b));
    g_s[j]  = s;
    g_wm[j] = w;
    g_bk[j] = b;
    atomicAdd(&g_hist[b], 1);
}

// K2: exclusive scan hist -> cur; zero hist for next replay; init chunk stats
__global__ __launch_bounds__(1024)
void scan_kernel() {
    __shared__ int warpsums[32];
    const int t = threadIdx.x, lane = t & 31, wid = t >> 5;

    int4 h = reinterpret_cast<const int4*>(g_hist)[t];           // buckets 4t..4t+3
    reinterpret_cast<int4*>(g_hist)[t] = make_int4(0, 0, 0, 0);  // ready for next run

    int lsum = h.x + h.y + h.z + h.w;
    int inc = lsum;
    #pragma unroll
    for (int off = 1; off < 32; off <<= 1) {
        int n = __shfl_up_sync(0xffffffffu, inc, off);
        if (lane >= off) inc += n;
    }
    if (lane == 31) warpsums[wid] = inc;
    __syncthreads();
    if (wid == 0) {
        int ws = warpsums[lane];
        int winc = ws;
        #pragma unroll
        for (int off = 1; off < 32; off <<= 1) {
            int n = __shfl_up_sync(0xffffffffu, winc, off);
            if (lane >= off) winc += n;
        }
        warpsums[lane] = winc - ws;   // exclusive warp offset
    }
    __syncthreads();
    int base = warpsums[wid] + (inc - lsum);
    int4 o;
    o.x = base;
    o.y = base + h.x;
    o.z = base + h.x + h.y;
    o.w = base + h.x + h.y + h.z;
    reinterpret_cast<int4*>(g_cur)[t] = o;

    if (t < NCHUNK) {
        g_csmin[t]  = 0x7F800000u;   // +inf
        g_cwmax[t]  = 0u;            // 0.0f (all w > 0)
        g_cnsmin[t] = 0xFFFFFFFFu;   // most-negative float bits
    }
}

// K3: scatter into sorted arrays; fold per-chunk stats in via bitwise atomics.
// s>0 and w>0 -> int bits monotone; -s*w<=0 -> uint bits reverse-monotone.
__global__ __launch_bounds__(128)
void scatter_kernel() {
    int j = blockIdx.x * 128 + threadIdx.x;
    float s = g_s[j];
    float w = g_wm[j];
    int pos = atomicAdd(&g_cur[g_bk[j]], 1);
    g_ss[pos]  = s;
    g_ws[pos]  = w;
    g_idx[pos] = j;
    int c = pos >> 5;
    atomicMin(&g_csmin[c],  __float_as_uint(s));
    atomicMax(&g_cwmax[c],  __float_as_uint(w));
    atomicMin(&g_cnsmin[c], __float_as_uint(-s * w));   // uint-min == float-max (negatives)
}

// K4: warp per row — groups of 4 chunks; 4 gathers in flight per group;
// strict in-order gating with the fully-reduced current best.
__global__ __launch_bounds__(256)
void probe_kernel(const int* __restrict__ adj, float* __restrict__ out) {
    __shared__ float s_cmin[NCHUNK], s_cwub[NCHUNK], s_cnsw[NCHUNK];

    const int t = threadIdx.x;
    const int lane = t & 31;
    const int warp = t >> 5;

    // Load raw chunk stats (hot L2) into smem
    s_cmin[t] = __uint_as_float(g_csmin[t]);
    s_cwub[t] = __uint_as_float(g_cwmax[t]);
    s_cnsw[t] = __uint_as_float(g_cnsmin[t]);
    __syncthreads();

    // Warp 0: in-place suffix scan over 256 chunks (8 per lane)
    if (t < 32) {
        float lm[8], lw[8], ln[8];
        float amn = 3.0e38f, amx = -3.0e38f, ans = -3.0e38f;
        #pragma unroll
        for (int q = 0; q < 8; q++) {
            lm[q] = s_cmin[t * 8 + q];
            lw[q] = s_cwub[t * 8 + q];
            ln[q] = s_cnsw[t * 8 + q];
            amn = fminf(amn, lm[q]);
            amx = fmaxf(amx, lw[q]);
            ans = fmaxf(ans, ln[q]);
        }
        float smn = amn, smx = amx, sns = ans;
        #pragma unroll
        for (int off = 1; off < 32; off <<= 1) {
            float a = __shfl_down_sync(0xffffffffu, smn, off);
            float b = __shfl_down_sync(0xffffffffu, smx, off);
            float c = __shfl_down_sync(0xffffffffu, sns, off);
            if (lane + off < 32) {
                smn = fminf(smn, a); smx = fmaxf(smx, b); sns = fmaxf(sns, c);
            }
        }
        float tmn = __shfl_down_sync(0xffffffffu, smn, 1);
        float tmx = __shfl_down_sync(0xffffffffu, smx, 1);
        float tns = __shfl_down_sync(0xffffffffu, sns, 1);
        if (lane == 31) { tmn = 3.0e38f; tmx = -3.0e38f; tns = -3.0e38f; }
        float rmn = tmn, rmx = tmx, rns = tns;
        #pragma unroll
        for (int q = 7; q >= 0; q--) {
            rmn = fminf(rmn, lm[q]);
            rmx = fmaxf(rmx, lw[q]);
            rns = fmaxf(rns, ln[q]);
            s_cmin[t * 8 + q] = rmn;
            s_cwub[t * 8 + q] = rmx;
            s_cnsw[t * 8 + q] = rns;
        }
    }
    __syncthreads();

    const int i = blockIdx.x * 8 + warp;
    const float si = g_s[i];
    const int* __restrict__ arow = adj + (size_t)i * NN;

    float best = 0.0f;   // reference max always includes T[i,i] = 0

    // Preload group 0 (chunks 0..3): 4 independent gathers in flight
    int a[GRP];
    #pragma unroll
    for (int q = 0; q < GRP; q++)
        a[q] = __ldg(&arow[g_idx[q * 32 + lane]]);

    for (int g = 0; g < NGRP; g++) {
        // Process group g (uses preloaded a[])
        float lb = 0.0f;
        #pragma unroll
        for (int q = 0; q < GRP; q++) {
            const int k = (g * GRP + q) * 32 + lane;
            float d = si - g_ss[k];
            if (d > 0.0f && a[q]) lb = fmaxf(lb, d * g_ws[k]);
        }
        #pragma unroll
        for (int off = 16; off; off >>= 1)
            lb = fmaxf(lb, __shfl_xor_sync(0xffffffffu, lb, off));
        best = fmaxf(best, lb);

        if (g + 1 < NGRP) {
            // Gate with the fully-current best; bounds are suffix-monotone.
            //  b1: (si - min s) * max w          (fp-monotone, exact-safe)
            //  b2: si*max(w) + max(-s*w) + slack (slack >> total rounding error)
            const int c = (g + 1) * GRP;
            float b1 = (si - s_cmin[c]) * s_cwub[c];
            float b2 = si * s_cwub[c] + s_cnsw[c] + 1e-5f;
            if (fminf(b1, b2) <= best) break;

            // Issue the next group's 4 gathers back-to-back
            #pragma unroll
            for (int q = 0; q < GRP; q++)
                a[q] = __ldg(&arow[g_idx[(c + q) * 32 + lane]]);
        }
    }

    if (lane == 0) {
        out[i * 3 + 0] = best;
        out[i * 3 + 1] = best;
        out[i * 3 + 2] = best;
    }
}

extern "C" void kernel_launch(void* const* d_in, const int* in_sizes, int n_in,
                              void* d_out, int out_size) {
    const float* x    = (const float*)d_in[0];
    const int*   adj  = (const int*)d_in[1];
    const float* Wphi = (const float*)d_in[2];
    // d_in[3] (W_theta) is unused in the forward pass.
    float* out = (float*)d_out;

    bucket_kernel<<<NN / 128, 128>>>(x, Wphi);
    scan_kernel<<<1, 1024>>>();
    scatter_kernel<<<NN / 128, 128>>>();
    probe_kernel<<<NN / 8, 256>>>(adj, out);
}

// round 13
// speedup vs baseline: 1.3072x; 1.3072x over previous
#include <cuda_runtime.h>
#include <cstdint>

#define NN 8192
#define KB 4096               // histogram buckets (fine sort -> tight bounds)
#define NCHUNK 256            // 256 chunks of 32 sorted candidates

// Scratch (device globals — no allocation allowed in kernel_launch).
// Zero-initialized at load; every array is re-established each launch chain.
__device__ float    g_s[NN];          // s[j] by original index
__device__ float    g_wm[NN];         // wmax[j] by original index
__device__ int      g_bk[NN];         // bucket id by original index
__device__ __align__(16) int g_hist[KB];  // histogram (re-zeroed by scan for next run)
__device__ __align__(16) int g_cur[KB];   // exclusive offsets -> scatter cursors
__device__ float    g_ss[NN];         // s in bucket-sorted order
__device__ float    g_ws[NN];         // wmax in bucket-sorted order
__device__ int      g_idx[NN];        // original index in bucket-sorted order
__device__ unsigned g_csmin[NCHUNK];  // per-chunk min s   (positive-float bits, atomicMin)
__device__ unsigned g_cwmax[NCHUNK];  // per-chunk max w   (positive-float bits, atomicMax)
__device__ unsigned g_cnsmin[NCHUNK]; // per-chunk max -s*w (negative-float bits, atomicMin)

// K1: per-element s, wmax, bucket; histogram via spread global atomics
__global__ __launch_bounds__(128)
void bucket_kernel(const float* __restrict__ x, const float* __restrict__ Wphi) {
    int j = blockIdx.x * 128 + threadIdx.x;
    float s = x[3 * j + 0] + x[3 * j + 1] + x[3 * j + 2];
    float w0 = Wphi[j], w1 = Wphi[NN + j], w2 = Wphi[2 * NN + j];
    float w = fmaxf(w0, fmaxf(w1, w2));
    int b = (int)(s * (KB / 3.0f));
    b = max(0, min(KB - 1, b));
    g_s[j]  = s;
    g_wm[j] = w;
    g_bk[j] = b;
    atomicAdd(&g_hist[b], 1);
}

// K2: exclusive scan hist -> cur; zero hist for next replay; init chunk stats
__global__ __launch_bounds__(1024)
void scan_kernel() {
    __shared__ int warpsums[32];
    const int t = threadIdx.x, lane = t & 31, wid = t >> 5;

    int4 h = reinterpret_cast<const int4*>(g_hist)[t];           // buckets 4t..4t+3
    reinterpret_cast<int4*>(g_hist)[t] = make_int4(0, 0, 0, 0);  // ready for next run

    int lsum = h.x + h.y + h.z + h.w;
    int inc = lsum;
    #pragma unroll
    for (int off = 1; off < 32; off <<= 1) {
        int n = __shfl_up_sync(0xffffffffu, inc, off);
        if (lane >= off) inc += n;
    }
    if (lane == 31) warpsums[wid] = inc;
    __syncthreads();
    if (wid == 0) {
        int ws = warpsums[lane];
        int winc = ws;
        #pragma unroll
        for (int off = 1; off < 32; off <<= 1) {
            int n = __shfl_up_sync(0xffffffffu, winc, off);
            if (lane >= off) winc += n;
        }
        warpsums[lane] = winc - ws;   // exclusive warp offset
    }
    __syncthreads();
    int base = warpsums[wid] + (inc - lsum);
    int4 o;
    o.x = base;
    o.y = base + h.x;
    o.z = base + h.x + h.y;
    o.w = base + h.x + h.y + h.z;
    reinterpret_cast<int4*>(g_cur)[t] = o;

    if (t < NCHUNK) {
        g_csmin[t]  = 0x7F800000u;   // +inf
        g_cwmax[t]  = 0u;            // 0.0f (all w > 0)
        g_cnsmin[t] = 0xFFFFFFFFu;   // most-negative float bits
    }
}

// K3: scatter into sorted arrays; fold per-chunk stats in via bitwise atomics.
// s>0 and w>0 -> int bits monotone; -s*w<=0 -> uint bits reverse-monotone.
__global__ __launch_bounds__(128)
void scatter_kernel() {
    int j = blockIdx.x * 128 + threadIdx.x;
    float s = g_s[j];
    float w = g_wm[j];
    int pos = atomicAdd(&g_cur[g_bk[j]], 1);
    g_ss[pos]  = s;
    g_ws[pos]  = w;
    g_idx[pos] = j;
    int c = pos >> 5;
    atomicMin(&g_csmin[c],  __float_as_uint(s));
    atomicMax(&g_cwmax[c],  __float_as_uint(w));
    atomicMin(&g_cnsmin[c], __float_as_uint(-s * w));   // uint-min == float-max (negatives)
}

// K4: warp per row — gate every chunk, 1-deep prefetch, per-lane potential
// pre-filter: only lanes whose potential exceeds the running best fetch
// adjacency (dominated candidates provably cannot change the max).
__global__ __launch_bounds__(256)
void probe_kernel(const int* __restrict__ adj, float* __restrict__ out) {
    __shared__ float s_cmin[NCHUNK], s_cwub[NCHUNK], s_cnsw[NCHUNK];

    const int t = threadIdx.x;
    const int lane = t & 31;
    const int warp = t >> 5;

    // Load raw chunk stats (hot L2) into smem
    s_cmin[t] = __uint_as_float(g_csmin[t]);
    s_cwub[t] = __uint_as_float(g_cwmax[t]);
    s_cnsw[t] = __uint_as_float(g_cnsmin[t]);
    __syncthreads();

    // Warp 0: in-place suffix scan over 256 chunks (8 per lane)
    if (t < 32) {
        float lm[8], lw[8], ln[8];
        float amn = 3.0e38f, amx = -3.0e38f, ans = -3.0e38f;
        #pragma unroll
        for (int q = 0; q < 8; q++) {
            lm[q] = s_cmin[t * 8 + q];
            lw[q] = s_cwub[t * 8 + q];
            ln[q] = s_cnsw[t * 8 + q];
            amn = fminf(amn, lm[q]);
            amx = fmaxf(amx, lw[q]);
            ans = fmaxf(ans, ln[q]);
        }
        float smn = amn, smx = amx, sns = ans;
        #pragma unroll
        for (int off = 1; off < 32; off <<= 1) {
            float a = __shfl_down_sync(0xffffffffu, smn, off);
            float b = __shfl_down_sync(0xffffffffu, smx, off);
            float c = __shfl_down_sync(0xffffffffu, sns, off);
            if (lane + off < 32) {
                smn = fminf(smn, a); smx = fmaxf(smx, b); sns = fmaxf(sns, c);
            }
        }
        float tmn = __shfl_down_sync(0xffffffffu, smn, 1);
        float tmx = __shfl_down_sync(0xffffffffu, smx, 1);
        float tns = __shfl_down_sync(0xffffffffu, sns, 1);
        if (lane == 31) { tmn = 3.0e38f; tmx = -3.0e38f; tns = -3.0e38f; }
        float rmn = tmn, rmx = tmx, rns = tns;
        #pragma unroll
        for (int q = 7; q >= 0; q--) {
            rmn = fminf(rmn, lm[q]);
            rmx = fmaxf(rmx, lw[q]);
            rns = fmaxf(rns, ln[q]);
            s_cmin[t * 8 + q] = rmn;
            s_cwub[t * 8 + q] = rmx;
            s_cnsw[t * 8 + q] = rns;
        }
    }
    __syncthreads();

    const int i = blockIdx.x * 8 + warp;
    const float si = g_s[i];
    const int* __restrict__ arow = adj + (size_t)i * NN;

    float best = 0.0f;   // reference max always includes T[i,i] = 0

    // Chunk 0: potential = (si - sj) * wj; fetch only lanes with pot > 0
    float pot = (si - g_ss[lane]) * g_ws[lane];
    int a = 0;
    if (pot > 0.0f) a = __ldg(&arow[g_idx[lane]]);

    for (int c = 0; c < NCHUNK; c++) {
        // Prefetch chunk c+1 with the pre-chunk-c best: superset of the lanes
        // that can matter (best only grows), so skipping the rest is exact.
        float npot = 0.0f;
        int   na = 0;
        if (c + 1 < NCHUNK) {
            const int k = (c + 1) * 32 + lane;
            npot = (si - g_ss[k]) * g_ws[k];
            if (npot > best) na = __ldg(&arow[g_idx[k]]);
        }

        // Process chunk c: contribution IS the potential (same fp expression
        // as the reference's positive branch); unfetched lanes are dominated.
        float contrib = (a != 0 && pot > 0.0f) ? pot : 0.0f;
        unsigned wm = __reduce_max_sync(0xffffffffu, __float_as_uint(contrib));
        best = fmaxf(best, __uint_as_float(wm));   // contrib >= 0: bits monotone

        if (c + 1 < NCHUNK) {
            // Two safe suffix bounds on all candidates in chunks >= c+1:
            //  b1: (si - min s) * max w          (fp-monotone, exact-safe)
            //  b2: si*max(w) + max(-s*w) + slack (slack >> total rounding error)
            float b1 = (si - s_cmin[c + 1]) * s_cwub[c + 1];
            float b2 = si * s_cwub[c + 1] + s_cnsw[c + 1] + 1e-5f;
            if (fminf(b1, b2) <= best) break;
            a = na;
            pot = npot;
        }
    }

    if (lane == 0) {
        out[i * 3 + 0] = best;
        out[i * 3 + 1] = best;
        out[i * 3 + 2] = best;
    }
}

extern "C" void kernel_launch(void* const* d_in, const int* in_sizes, int n_in,
                              void* d_out, int out_size) {
    const float* x    = (const float*)d_in[0];
    const int*   adj  = (const int*)d_in[1];
    const float* Wphi = (const float*)d_in[2];
    // d_in[3] (W_theta) is unused in the forward pass.
    float* out = (float*)d_out;

    bucket_kernel<<<NN / 128, 128>>>(x, Wphi);
    scan_kernel<<<1, 1024>>>();
    scatter_kernel<<<NN / 128, 128>>>();
    probe_kernel<<<NN / 8, 256>>>(adj, out);
}

// round 14
// speedup vs baseline: 1.3182x; 1.0084x over previous
#include <cuda_runtime.h>
#include <cstdint>

#define NN 8192
#define KB 4096               // histogram buckets (fine sort -> tight bounds)
#define NCHUNK 256            // 256 chunks of 32 sorted candidates

// Scratch (device globals — no allocation allowed in kernel_launch).
// Zero-initialized at load; every array is re-established each launch chain.
__device__ float    g_s[NN];          // s[j] by original index
__device__ float    g_wm[NN];         // wmax[j] by original index
__device__ int      g_bk[NN];         // bucket id by original index
__device__ __align__(16) int g_hist[KB];  // histogram (re-zeroed by scan for next run)
__device__ __align__(16) int g_cur[KB];   // exclusive offsets -> scatter cursors
__device__ float    g_ss[NN];         // s in bucket-sorted order
__device__ float    g_ws[NN];         // wmax in bucket-sorted order
__device__ int      g_idx[NN];        // original index in bucket-sorted order
__device__ unsigned g_csmin[NCHUNK];  // per-chunk min s   (positive-float bits, atomicMin)
__device__ unsigned g_cwmax[NCHUNK];  // per-chunk max w   (positive-float bits, atomicMax)
__device__ unsigned g_cnsmin[NCHUNK]; // per-chunk max -s*w (negative-float bits, atomicMin)

// K1: per-element s, wmax, bucket; histogram via spread global atomics
__global__ __launch_bounds__(128)
void bucket_kernel(const float* __restrict__ x, const float* __restrict__ Wphi) {
    int j = blockIdx.x * 128 + threadIdx.x;
    float s = x[3 * j + 0] + x[3 * j + 1] + x[3 * j + 2];
    float w0 = Wphi[j], w1 = Wphi[NN + j], w2 = Wphi[2 * NN + j];
    float w = fmaxf(w0, fmaxf(w1, w2));
    int b = (int)(s * (KB / 3.0f));
    b = max(0, min(KB - 1, b));
    g_s[j]  = s;
    g_wm[j] = w;
    g_bk[j] = b;
    atomicAdd(&g_hist[b], 1);
}

// K2: exclusive scan hist -> cur; zero hist for next replay; init chunk stats
__global__ __launch_bounds__(1024)
void scan_kernel() {
    __shared__ int warpsums[32];
    const int t = threadIdx.x, lane = t & 31, wid = t >> 5;

    int4 h = reinterpret_cast<const int4*>(g_hist)[t];           // buckets 4t..4t+3
    reinterpret_cast<int4*>(g_hist)[t] = make_int4(0, 0, 0, 0);  // ready for next run

    int lsum = h.x + h.y + h.z + h.w;
    int inc = lsum;
    #pragma unroll
    for (int off = 1; off < 32; off <<= 1) {
        int n = __shfl_up_sync(0xffffffffu, inc, off);
        if (lane >= off) inc += n;
    }
    if (lane == 31) warpsums[wid] = inc;
    __syncthreads();
    if (wid == 0) {
        int ws = warpsums[lane];
        int winc = ws;
        #pragma unroll
        for (int off = 1; off < 32; off <<= 1) {
            int n = __shfl_up_sync(0xffffffffu, winc, off);
            if (lane >= off) winc += n;
        }
        warpsums[lane] = winc - ws;   // exclusive warp offset
    }
    __syncthreads();
    int base = warpsums[wid] + (inc - lsum);
    int4 o;
    o.x = base;
    o.y = base + h.x;
    o.z = base + h.x + h.y;
    o.w = base + h.x + h.y + h.z;
    reinterpret_cast<int4*>(g_cur)[t] = o;

    if (t < NCHUNK) {
        g_csmin[t]  = 0x7F800000u;   // +inf
        g_cwmax[t]  = 0u;            // 0.0f (all w > 0)
        g_cnsmin[t] = 0xFFFFFFFFu;   // most-negative float bits
    }
}

// K3: scatter into sorted arrays; fold per-chunk stats in via bitwise atomics.
// s>0 and w>0 -> int bits monotone; -s*w<=0 -> uint bits reverse-monotone.
__global__ __launch_bounds__(128)
void scatter_kernel() {
    int j = blockIdx.x * 128 + threadIdx.x;
    float s = g_s[j];
    float w = g_wm[j];
    int pos = atomicAdd(&g_cur[g_bk[j]], 1);
    g_ss[pos]  = s;
    g_ws[pos]  = w;
    g_idx[pos] = j;
    int c = pos >> 5;
    atomicMin(&g_csmin[c],  __float_as_uint(s));
    atomicMax(&g_cwmax[c],  __float_as_uint(w));
    atomicMin(&g_cnsmin[c], __float_as_uint(-s * w));   // uint-min == float-max (negatives)
}

// K4: warp per row — wide 3-chunk start (one latency covers three chunks),
// then R8's gate-every-chunk + 1-deep-prefetch loop. REDUX for the reduce.
__global__ __launch_bounds__(256)
void probe_kernel(const int* __restrict__ adj, float* __restrict__ out) {
    __shared__ float s_cmin[NCHUNK], s_cwub[NCHUNK], s_cnsw[NCHUNK];

    const int t = threadIdx.x;
    const int lane = t & 31;
    const int warp = t >> 5;

    // Load raw chunk stats (hot L2) into smem
    s_cmin[t] = __uint_as_float(g_csmin[t]);
    s_cwub[t] = __uint_as_float(g_cwmax[t]);
    s_cnsw[t] = __uint_as_float(g_cnsmin[t]);
    __syncthreads();

    // Warp 0: in-place suffix scan over 256 chunks (8 per lane)
    if (t < 32) {
        float lm[8], lw[8], ln[8];
        float amn = 3.0e38f, amx = -3.0e38f, ans = -3.0e38f;
        #pragma unroll
        for (int q = 0; q < 8; q++) {
            lm[q] = s_cmin[t * 8 + q];
            lw[q] = s_cwub[t * 8 + q];
            ln[q] = s_cnsw[t * 8 + q];
            amn = fminf(amn, lm[q]);
            amx = fmaxf(amx, lw[q]);
            ans = fmaxf(ans, ln[q]);
        }
        float smn = amn, smx = amx, sns = ans;
        #pragma unroll
        for (int off = 1; off < 32; off <<= 1) {
            float a = __shfl_down_sync(0xffffffffu, smn, off);
            float b = __shfl_down_sync(0xffffffffu, smx, off);
            float c = __shfl_down_sync(0xffffffffu, sns, off);
            if (lane + off < 32) {
                smn = fminf(smn, a); smx = fmaxf(smx, b); sns = fmaxf(sns, c);
            }
        }
        float tmn = __shfl_down_sync(0xffffffffu, smn, 1);
        float tmx = __shfl_down_sync(0xffffffffu, smx, 1);
        float tns = __shfl_down_sync(0xffffffffu, sns, 1);
        if (lane == 31) { tmn = 3.0e38f; tmx = -3.0e38f; tns = -3.0e38f; }
        float rmn = tmn, rmx = tmx, rns = tns;
        #pragma unroll
        for (int q = 7; q >= 0; q--) {
            rmn = fminf(rmn, lm[q]);
            rmx = fmaxf(rmx, lw[q]);
            rns = fmaxf(rns, ln[q]);
            s_cmin[t * 8 + q] = rmn;
            s_cwub[t * 8 + q] = rmx;
            s_cnsw[t * 8 + q] = rns;
        }
    }
    __syncthreads();

    const int i = blockIdx.x * 8 + warp;
    const float si = g_s[i];
    const int* __restrict__ arow = adj + (size_t)i * NN;

    float best = 0.0f;   // reference max always includes T[i,i] = 0

    // Wide start: chunks 0..2 issued back-to-back (one DRAM latency, MLP=3)
    int a0 = __ldg(&arow[g_idx[0 * 32 + lane]]);
    int a1 = __ldg(&arow[g_idx[1 * 32 + lane]]);
    int a2 = __ldg(&arow[g_idx[2 * 32 + lane]]);

    // Process a chunk: contribution = (si - sj)*wj if neighbor & positive.
    // REDUX on float bits is exact for nonnegative floats (bit order = value order).
    #define PROC_CHUNK(cc, av)                                                  \
    {                                                                           \
        const int k_ = (cc) * 32 + lane;                                        \
        float d_ = si - g_ss[k_];                                               \
        float ct_ = (d_ > 0.0f && (av)) ? d_ * g_ws[k_] : 0.0f;                 \
        unsigned wm_ = __reduce_max_sync(0xffffffffu, __float_as_uint(ct_));    \
        best = fmaxf(best, __uint_as_float(wm_));                               \
    }

    PROC_CHUNK(0, a0)
    PROC_CHUNK(1, a1)
    PROC_CHUNK(2, a2)

    // Continue from chunk 3 only if the suffix can still matter.
    //  b1: (si - min s) * max w          (fp-monotone, exact-safe)
    //  b2: si*max(w) + max(-s*w) + slack (slack >> total rounding error)
    {
        float b1 = (si - s_cmin[3]) * s_cwub[3];
        float b2 = si * s_cwub[3] + s_cnsw[3] + 1e-5f;
        if (fminf(b1, b2) > best) {
            int a = __ldg(&arow[g_idx[3 * 32 + lane]]);
            for (int c = 3; c < NCHUNK; c++) {
                // 1-deep prefetch of the next chunk (overlaps this chunk's work)
                int na = 0;
                if (c + 1 < NCHUNK)
                    na = __ldg(&arow[g_idx[(c + 1) * 32 + lane]]);

                PROC_CHUNK(c, a)

                if (c + 1 < NCHUNK) {
                    float nb1 = (si - s_cmin[c + 1]) * s_cwub[c + 1];
                    float nb2 = si * s_cwub[c + 1] + s_cnsw[c + 1] + 1e-5f;
                    if (fminf(nb1, nb2) <= best) break;
                    a = na;
                }
            }
        }
    }
    #undef PROC_CHUNK

    if (lane == 0) {
        out[i * 3 + 0] = best;
        out[i * 3 + 1] = best;
        out[i * 3 + 2] = best;
    }
}

extern "C" void kernel_launch(void* const* d_in, const int* in_sizes, int n_in,
                              void* d_out, int out_size) {
    const float* x    = (const float*)d_in[0];
    const int*   adj  = (const int*)d_in[1];
    const float* Wphi = (const float*)d_in[2];
    // d_in[3] (W_theta) is unused in the forward pass.
    float* out = (float*)d_out;

    bucket_kernel<<<NN / 128, 128>>>(x, Wphi);
    scan_kernel<<<1, 1024>>>();
    scatter_kernel<<<NN / 128, 128>>>();
    probe_kernel<<<NN / 8, 256>>>(adj, out);
}